// round 14
// baseline (speedup 1.0000x reference)
#include <cuda_runtime.h>
#include <cstdint>

// CRF_14379550507279 fixed shapes:
//   emissions (B=512, S=2048, T=32) f32, tags (B,S) i32, mask (B,S) f32,
//   transitions (32,32) f32. Output: scalar f32.
//
// total = sum_{all b,s,t} mask[b,s]*em[b,s,t]                                (phase 2)
//       + sum_b [ (1-mask[b,0])*sum_t em[b,0,t] + sum_t trans[tags[b,0],t] ] (phase 1b)
//       + 32 * sum_{b,s>=1} trans[tags[b,s-1],tags[b,s]] * mask[b,s]         (phase 1a)

#define NTAGS 32
#define B_DIM 512
#define S_DIM 2048
#define BS_ROWS (B_DIM * S_DIM)              // 1048576 rows of 128 B
#define TOTAL_C8 (BS_ROWS * 4)               // 4194304 32-byte chunks

#define GRID 1184                            // 148 SMs * 8 CTAs, one wave
#define BLOCK 128
#define NT (GRID * BLOCK)                    // 151552 threads

#define TILE_C8 256                          // per-warp tile: 8 KB, 8 chunks/lane
#define N_STILES (TOTAL_C8 / TILE_C8)        // 16384 tiles, exact

__device__ double g_acc = 0.0;
__device__ unsigned int g_count = 0;
__device__ unsigned int g_tile = 0;          // work-stealing cursor

__device__ __forceinline__ float hsum4(float4 v) {
    return (v.x + v.y) + (v.z + v.w);
}

struct f8 { float4 a, b; };

// 256-bit streaming read: bypass L1, evict-first in L2 (no reuse)
__device__ __forceinline__ f8 ldg_stream256(const float* p) {
    f8 v;
    asm("ld.global.nc.L2::evict_first.v8.b32 "
        "{%0,%1,%2,%3,%4,%5,%6,%7}, [%8];"
        : "=f"(v.a.x), "=f"(v.a.y), "=f"(v.a.z), "=f"(v.a.w),
          "=f"(v.b.x), "=f"(v.b.y), "=f"(v.b.z), "=f"(v.b.w)
        : "l"(p));
    return v;
}

__device__ __forceinline__ float hsum8(f8 v) {
    return hsum4(v.a) + hsum4(v.b);
}

__global__ void __launch_bounds__(BLOCK, 8) crf_fused_kernel(
    const float* __restrict__ em,      // B*S*32 floats
    const int* __restrict__ tags,      // B*S
    const float* __restrict__ mask,    // B*S
    const float* __restrict__ trans,   // 32*32
    float* __restrict__ out)
{
    __shared__ float s_trans[NTAGS * NTAGS];
    __shared__ float warp_sums[BLOCK / 32];

    const int tid = threadIdx.x;
    const int lane = tid & 31;
    const int gtid = blockIdx.x * BLOCK + tid;

    for (int i = tid; i < NTAGS * NTAGS; i += BLOCK)
        s_trans[i] = trans[i];
    __syncthreads();

    float acc = 0.0f;

    // ---- Phase 1a: transition steps, branch-free, full-grid (bandwidth-bound).
    for (int row = gtid; row < BS_ROWS; row += NT) {
        const int s = row & (S_DIM - 1);
        const int tc = __ldg(&tags[row]);
        const int tp = __ldg(&tags[(row > 0) ? (row - 1) : 0]);
        const float w = (s == 0) ? 0.0f : __ldg(&mask[row]);
        // scalar trans broadcast over T columns -> counted NTAGS times
        acc += (float)NTAGS * s_trans[tp * NTAGS + tc] * w;
    }

    // ---- Phase 1b: s==0 specials (512 terms, one thread per batch).
    if (gtid < B_DIM) {
        const int row = gtid * S_DIM;
        const int tc = __ldg(&tags[row]);
        const float m = __ldg(&mask[row]);
        float ts = 0.0f;
        #pragma unroll
        for (int t = 0; t < NTAGS; t++) ts += s_trans[tc * NTAGS + t];
        float es = 0.0f;
        const float4* p = (const float4*)(em + (size_t)row * 32);
        #pragma unroll
        for (int i = 0; i < 8; i++) es += hsum4(__ldg(p + i));
        // phase 2 weights this row by mask[b,0]; reference wants weight 1
        acc += ts + (1.0f - m) * es;
    }

    // ---- Phase 2: warp work-stealing over 8 KB emission tiles.
    {
        float a0 = 0.0f, a1 = 0.0f, a2 = 0.0f, a3 = 0.0f;

        unsigned int t;
        if (lane == 0) t = atomicAdd(&g_tile, 1u);
        t = __shfl_sync(0xffffffffu, t, 0);

        while (t < N_STILES) {
            // prefetch next tile index to hide ATOMG latency
            unsigned int tn;
            if (lane == 0) tn = atomicAdd(&g_tile, 1u);
            tn = __shfl_sync(0xffffffffu, tn, 0);

            const unsigned int base = t * TILE_C8;          // 32B-chunk index
            const float* bp = em + (size_t)base * 8 + lane * 8;
            const int mbase = (base >> 2) + (lane >> 2);    // row index base
            // 8 chunks/lane: j=0..7, chunk = base + lane + j*32
            const f8 v0 = ldg_stream256(bp + 0 * 256);
            const f8 v1 = ldg_stream256(bp + 1 * 256);
            const f8 v2 = ldg_stream256(bp + 2 * 256);
            const f8 v3 = ldg_stream256(bp + 3 * 256);
            const f8 v4 = ldg_stream256(bp + 4 * 256);
            const f8 v5 = ldg_stream256(bp + 5 * 256);
            const f8 v6 = ldg_stream256(bp + 6 * 256);
            const f8 v7 = ldg_stream256(bp + 7 * 256);
            const float m0 = __ldg(&mask[mbase + 0 * 8]);
            const float m1 = __ldg(&mask[mbase + 1 * 8]);
            const float m2 = __ldg(&mask[mbase + 2 * 8]);
            const float m3 = __ldg(&mask[mbase + 3 * 8]);
            const float m4 = __ldg(&mask[mbase + 4 * 8]);
            const float m5 = __ldg(&mask[mbase + 5 * 8]);
            const float m6 = __ldg(&mask[mbase + 6 * 8]);
            const float m7 = __ldg(&mask[mbase + 7 * 8]);
            a0 += m0 * hsum8(v0);
            a1 += m1 * hsum8(v1);
            a2 += m2 * hsum8(v2);
            a3 += m3 * hsum8(v3);
            a0 += m4 * hsum8(v4);
            a1 += m5 * hsum8(v5);
            a2 += m6 * hsum8(v6);
            a3 += m7 * hsum8(v7);

            t = tn;
        }
        acc += (a0 + a1) + (a2 + a3);
    }

    // ---- Reduce: warp tree -> block -> global double atomic.
    #pragma unroll
    for (int o = 16; o > 0; o >>= 1)
        acc += __shfl_xor_sync(0xffffffffu, acc, o);

    const int wid = tid >> 5;
    if (lane == 0) warp_sums[wid] = acc;
    __syncthreads();

    if (tid == 0) {
        float b = 0.0f;
        #pragma unroll
        for (int i = 0; i < BLOCK / 32; i++) b += warp_sums[i];
        atomicAdd(&g_acc, (double)b);
        __threadfence();
        // last block finalizes: write scalar, reset state for next graph replay
        const unsigned int ticket = atomicInc(&g_count, GRID - 1);
        if (ticket == GRID - 1) {
            out[0] = (float)atomicAdd(&g_acc, 0.0);
            g_acc = 0.0;
            g_tile = 0;
        }
    }
}

extern "C" void kernel_launch(void* const* d_in, const int* in_sizes, int n_in,
                              void* d_out, int out_size) {
    const float* emissions   = (const float*)d_in[0];
    const int*   tags        = (const int*)d_in[1];
    const float* mask        = (const float*)d_in[2];
    const float* transitions = (const float*)d_in[3];

    crf_fused_kernel<<<GRID, BLOCK>>>(
        emissions, tags, mask, transitions, (float*)d_out);
}